// round 15
// baseline (speedup 1.0000x reference)
#include <cuda_runtime.h>
#include <cuda_bf16.h>
#include <cstddef>

#define NN 4096
#define CAP 192

// ---------------- device scratch ----------------
__device__ float g_h [NN*64];
__device__ float g_t1[NN*64];
__device__ float g_t2[NN*64];
__device__ float g_A2[NN*64];
__device__ float g_B2[NN*64];
__device__ float g_Wca[64*64];
__device__ float g_Wcb[64*64];
__device__ float g_c2[64];
__device__ int   g_cnt[NN];
__device__ int   g_col[NN*CAP];

// =====================================================================
// K1: encoder + gl1/gr1 projection | We-fold | bucket fill  (verified)
// =====================================================================
__global__ void __launch_bounds__(256)
k_prep(const float* __restrict__ x, const int* __restrict__ src, const int* __restrict__ dst,
       const float* __restrict__ W1,  const float* __restrict__ b1,
       const float* __restrict__ W2,  const float* __restrict__ b2,
       const float* __restrict__ Wl1, const float* __restrict__ bl1,
       const float* __restrict__ Wr1, const float* __restrict__ br1,
       const float* __restrict__ We1, const float* __restrict__ be1,
       const float* __restrict__ We2, const float* __restrict__ be2,
       int E)
{
    __shared__ float spool[4096];
    const int bid = blockIdx.x, tid = threadIdx.x;

    if (bid < 256) {
        __shared__ float xs[16][16];
        __shared__ float hs[16][64];
        const int j = tid & 63, rg = tid >> 6;
        const int rowb = bid*16;
        float w[32];
        {
            const int rr = tid >> 4, cc = tid & 15;
            xs[rr][cc] = x[(rowb + rr)*16 + cc];
        }
        float w1[16];
#pragma unroll
        for (int k = 0; k < 16; k++) w1[k] = W1[k*64 + j];
        const float b1j = b1[j];
        __syncthreads();
        float a0 = b1j, a1 = b1j, a2 = b1j, a3 = b1j;
#pragma unroll
        for (int k = 0; k < 16; k++) {
            const float wk = w1[k];
            a0 = fmaf(xs[rg   ][k], wk, a0);
            a1 = fmaf(xs[rg+4 ][k], wk, a1);
            a2 = fmaf(xs[rg+8 ][k], wk, a2);
            a3 = fmaf(xs[rg+12][k], wk, a3);
        }
        const float h0 = fmaxf(a0, 0.f), h1 = fmaxf(a1, 0.f);
        const float h2 = fmaxf(a2, 0.f), h3 = fmaxf(a3, 0.f);
        hs[rg   ][j] = h0;  hs[rg+4 ][j] = h1;
        hs[rg+8 ][j] = h2;  hs[rg+12][j] = h3;
        __syncthreads();
        float c0 = b2[j], c1 = c0, c2 = c0, c3 = c0;
#pragma unroll
        for (int k = 0; k < 32; k++) w[k] = W2[k*64 + j];
#pragma unroll
        for (int k = 0; k < 32; k++) {
            const float wk = w[k];
            c0 = fmaf(hs[rg   ][k], wk, c0);
            c1 = fmaf(hs[rg+4 ][k], wk, c1);
            c2 = fmaf(hs[rg+8 ][k], wk, c2);
            c3 = fmaf(hs[rg+12][k], wk, c3);
        }
#pragma unroll
        for (int k = 0; k < 32; k++) w[k] = W2[(k+32)*64 + j];
#pragma unroll
        for (int k = 0; k < 32; k++) {
            const float wk = w[k];
            c0 = fmaf(hs[rg   ][k+32], wk, c0);
            c1 = fmaf(hs[rg+4 ][k+32], wk, c1);
            c2 = fmaf(hs[rg+8 ][k+32], wk, c2);
            c3 = fmaf(hs[rg+12][k+32], wk, c3);
        }
        const float f0 = h0 + fmaxf(c0, 0.f);
        const float f1 = h1 + fmaxf(c1, 0.f);
        const float f2 = h2 + fmaxf(c2, 0.f);
        const float f3 = h3 + fmaxf(c3, 0.f);
        g_h[(rowb+rg   )*64 + j] = f0;
        g_h[(rowb+rg+4 )*64 + j] = f1;
        g_h[(rowb+rg+8 )*64 + j] = f2;
        g_h[(rowb+rg+12)*64 + j] = f3;
        __syncthreads();
        hs[rg   ][j] = f0;  hs[rg+4 ][j] = f1;
        hs[rg+8 ][j] = f2;  hs[rg+12][j] = f3;
        __syncthreads();
        float l0 = bl1[j], l1 = l0, l2 = l0, l3 = l0;
#pragma unroll
        for (int k = 0; k < 32; k++) w[k] = Wl1[k*64 + j];
#pragma unroll
        for (int k = 0; k < 32; k++) {
            const float wk = w[k];
            l0 = fmaf(hs[rg   ][k], wk, l0);
            l1 = fmaf(hs[rg+4 ][k], wk, l1);
            l2 = fmaf(hs[rg+8 ][k], wk, l2);
            l3 = fmaf(hs[rg+12][k], wk, l3);
        }
#pragma unroll
        for (int k = 0; k < 32; k++) w[k] = Wl1[(k+32)*64 + j];
#pragma unroll
        for (int k = 0; k < 32; k++) {
            const float wk = w[k];
            l0 = fmaf(hs[rg   ][k+32], wk, l0);
            l1 = fmaf(hs[rg+4 ][k+32], wk, l1);
            l2 = fmaf(hs[rg+8 ][k+32], wk, l2);
            l3 = fmaf(hs[rg+12][k+32], wk, l3);
        }
        g_t1[(rowb+rg   )*64 + j] = l0;
        g_t1[(rowb+rg+4 )*64 + j] = l1;
        g_t1[(rowb+rg+8 )*64 + j] = l2;
        g_t1[(rowb+rg+12)*64 + j] = l3;
        float r0 = br1[j], r1 = r0, r2 = r0, r3 = r0;
#pragma unroll
        for (int k = 0; k < 32; k++) w[k] = Wr1[k*64 + j];
#pragma unroll
        for (int k = 0; k < 32; k++) {
            const float wk = w[k];
            r0 = fmaf(hs[rg   ][k], wk, r0);
            r1 = fmaf(hs[rg+4 ][k], wk, r1);
            r2 = fmaf(hs[rg+8 ][k], wk, r2);
            r3 = fmaf(hs[rg+12][k], wk, r3);
        }
#pragma unroll
        for (int k = 0; k < 32; k++) w[k] = Wr1[(k+32)*64 + j];
#pragma unroll
        for (int k = 0; k < 32; k++) {
            const float wk = w[k];
            r0 = fmaf(hs[rg   ][k+32], wk, r0);
            r1 = fmaf(hs[rg+4 ][k+32], wk, r1);
            r2 = fmaf(hs[rg+8 ][k+32], wk, r2);
            r3 = fmaf(hs[rg+12][k+32], wk, r3);
        }
        g_t2[(rowb+rg   )*64 + j] = r0;
        g_t2[(rowb+rg+4 )*64 + j] = r1;
        g_t2[(rowb+rg+8 )*64 + j] = r2;
        g_t2[(rowb+rg+12)*64 + j] = r3;
    } else if (bid < 258) {
        const int fb = bid - 256;
        for (int idx = tid; idx < 4096; idx += 256) spool[idx] = We2[idx];
        __syncthreads();
        const int j = tid & 63, il = tid >> 6;
        for (int pass = 0; pass < 8; pass++) {
            const int i = fb*32 + pass*4 + il;
            float sa = 0.f, sb = 0.f;
#pragma unroll
            for (int m = 0; m < 64; m++) {
                const float w2v = spool[m*64 + j];
                sa = fmaf(We1[i*64 + m],      w2v, sa);
                sb = fmaf(We1[(64+i)*64 + m], w2v, sb);
            }
            g_Wca[i*64 + j] = sa;
            g_Wcb[i*64 + j] = sb;
        }
        if (fb == 0 && tid < 64) {
            float cc = be2[tid];
            for (int m = 0; m < 64; m++) cc = fmaf(be1[m], spool[m*64 + tid], cc);
            g_c2[tid] = cc;
        }
    } else {
        for (int e = (bid - 258)*256 + tid; e < E; e += 64*256) {
            const int d = dst[e];
            const int p = atomicAdd(&g_cnt[d], 1);
            if (p < CAP) g_col[d*CAP + p] = src[e];
        }
    }
}

// =====================================================================
// fused residual + dual projection (verified)
// =====================================================================
__global__ void __launch_bounds__(256)
k_resdual(float* __restrict__ H,
          const float* __restrict__ Wres, const float* __restrict__ bres,
          const float* __restrict__ Wa, const float* __restrict__ ba,
          const float* __restrict__ Wb, const float* __restrict__ bb,
          float* __restrict__ Ya, float* __restrict__ Yb)
{
    __shared__ float xs[8][64];
    float w[32];
    const int rowb = blockIdx.x*8;
    for (int idx = threadIdx.x; idx < 512; idx += 256)
        xs[idx >> 6][idx & 63] = H[rowb*64 + idx];

    {
        const int j  = threadIdx.x & 63;
        const int rg = threadIdx.x >> 6;
#pragma unroll
        for (int k = 0; k < 32; k++) w[k] = Wres[k*64 + j];
        const float bj = bres[j];
        __syncthreads();
        float r0 = bj, r1 = bj;
#pragma unroll
        for (int k = 0; k < 32; k++) {
            const float wk = w[k];
            r0 = fmaf(xs[rg  ][k], wk, r0);
            r1 = fmaf(xs[rg+4][k], wk, r1);
        }
#pragma unroll
        for (int k = 0; k < 32; k++) w[k] = Wres[(k+32)*64 + j];
#pragma unroll
        for (int k = 0; k < 32; k++) {
            const float wk = w[k];
            r0 = fmaf(xs[rg  ][k+32], wk, r0);
            r1 = fmaf(xs[rg+4][k+32], wk, r1);
        }
        const float hn0 = xs[rg  ][j] + fmaxf(r0, 0.f);
        const float hn1 = xs[rg+4][j] + fmaxf(r1, 0.f);
        __syncthreads();
        xs[rg  ][j] = hn0;
        xs[rg+4][j] = hn1;
        H[(rowb+rg  )*64 + j] = hn0;
        H[(rowb+rg+4)*64 + j] = hn1;
    }
    __syncthreads();

    {
        const int jj  = threadIdx.x & 127;
        const int grp = jj >> 6;
        const int j   = jj & 63;
        const int rg  = threadIdx.x >> 7;
        const float* W = grp ? Wb : Wa;
        const float* B = grp ? bb : ba;
        float*       Y = grp ? Yb : Ya;
        const float b = B ? B[j] : 0.f;
        float a0 = b, a1 = b, a2 = b, a3 = b;
#pragma unroll
        for (int k = 0; k < 32; k++) w[k] = W[k*64 + j];
#pragma unroll
        for (int k = 0; k < 32; k++) {
            const float wk = w[k];
            a0 = fmaf(xs[rg  ][k], wk, a0);
            a1 = fmaf(xs[rg+2][k], wk, a1);
            a2 = fmaf(xs[rg+4][k], wk, a2);
            a3 = fmaf(xs[rg+6][k], wk, a3);
        }
#pragma unroll
        for (int k = 0; k < 32; k++) w[k] = W[(k+32)*64 + j];
#pragma unroll
        for (int k = 0; k < 32; k++) {
            const float wk = w[k];
            a0 = fmaf(xs[rg  ][k+32], wk, a0);
            a1 = fmaf(xs[rg+2][k+32], wk, a1);
            a2 = fmaf(xs[rg+4][k+32], wk, a2);
            a3 = fmaf(xs[rg+6][k+32], wk, a3);
        }
        Y[(rowb+rg  )*64 + j] = a0;
        Y[(rowb+rg+2)*64 + j] = a1;
        Y[(rowb+rg+4)*64 + j] = a2;
        Y[(rowb+rg+6)*64 + j] = a3;
    }
}

// =====================================================================
// GAT attention v3: float4 lanes, fixed m0, 8 edges/iter with int4
// index loads (4 gathers in flight per half-warp)
// =====================================================================
__device__ __forceinline__ float lrelu_dot(float4 g, float4 grv, float4 attv)
{
    float sx = g.x + grv.x, sy = g.y + grv.y, sz = g.z + grv.z, sw = g.w + grv.w;
    sx = sx > 0.f ? sx : 0.2f*sx;
    sy = sy > 0.f ? sy : 0.2f*sy;
    sz = sz > 0.f ? sz : 0.2f*sz;
    sw = sw > 0.f ? sw : 0.2f*sw;
    return sx*attv.x + sy*attv.y + sz*attv.z + sw*attv.w;
}

__global__ void __launch_bounds__(256)
k_gat(const float* __restrict__ gl, const float* __restrict__ gr,
      const float* __restrict__ att, const float* __restrict__ cb,
      float* __restrict__ H)
{
    __shared__ float  sden[4][16];
    __shared__ float4 sv[4][16];
    const int w = threadIdx.x >> 5, lane = threadIdx.x & 31;
    const int nb = w >> 1, half = w & 1;
    const int i = blockIdx.x*4 + nb;
    const int eslot = lane >> 4;
    const int t = lane & 15;
    const int ch = t*4;

    const float4 attv = *(const float4*)&att[ch];
    const float4 grv  = *(const float4*)&gr[i*64 + ch];
    const float4 gs   = *(const float4*)&gl[i*64 + ch];

    float m0;
    {
        float e = lrelu_dot(gs, grv, attv);
        e += __shfl_xor_sync(0xffffffffu, e, 1);
        e += __shfl_xor_sync(0xffffffffu, e, 2);
        m0 = e;
    }
    float den = 0.f;
    float4 v = make_float4(0.f, 0.f, 0.f, 0.f);
    if (half == 0 && eslot == 0) { den = 1.f; v = gs; }

    const int cnt  = min(g_cnt[i], CAP);
    const int base = i*CAP;
    const int mid  = (cnt >> 1) & ~3;          // 4-aligned split
    const int lo   = half ? mid : 0;
    const int hi   = half ? cnt : mid;
    int p = lo;
    // main loop: 8 edges per warp-iter; this half-warp handles 4 via int4 index load
    for (; p + 8 <= hi; p += 8) {
        const int4 idx = *(const int4*)&g_col[base + p + eslot*4];
        const float4 ga = *(const float4*)&gl[idx.x*64 + ch];
        const float4 gb = *(const float4*)&gl[idx.y*64 + ch];
        const float4 gc = *(const float4*)&gl[idx.z*64 + ch];
        const float4 gd = *(const float4*)&gl[idx.w*64 + ch];
        float e0 = lrelu_dot(ga, grv, attv);
        float e1 = lrelu_dot(gb, grv, attv);
        float e2 = lrelu_dot(gc, grv, attv);
        float e3 = lrelu_dot(gd, grv, attv);
        e0 += __shfl_xor_sync(0xffffffffu, e0, 1);
        e1 += __shfl_xor_sync(0xffffffffu, e1, 1);
        e2 += __shfl_xor_sync(0xffffffffu, e2, 1);
        e3 += __shfl_xor_sync(0xffffffffu, e3, 1);
        e0 += __shfl_xor_sync(0xffffffffu, e0, 2);
        e1 += __shfl_xor_sync(0xffffffffu, e1, 2);
        e2 += __shfl_xor_sync(0xffffffffu, e2, 2);
        e3 += __shfl_xor_sync(0xffffffffu, e3, 2);
        const float w0 = __expf(e0 - m0);
        const float w1 = __expf(e1 - m0);
        const float w2 = __expf(e2 - m0);
        const float w3 = __expf(e3 - m0);
        den += (w0 + w1) + (w2 + w3);
        v.x = fmaf(w0, ga.x, fmaf(w1, gb.x, fmaf(w2, gc.x, fmaf(w3, gd.x, v.x))));
        v.y = fmaf(w0, ga.y, fmaf(w1, gb.y, fmaf(w2, gc.y, fmaf(w3, gd.y, v.y))));
        v.z = fmaf(w0, ga.z, fmaf(w1, gb.z, fmaf(w2, gc.z, fmaf(w3, gd.z, v.z))));
        v.w = fmaf(w0, ga.w, fmaf(w1, gb.w, fmaf(w2, gc.w, fmaf(w3, gd.w, v.w))));
    }
    // tail: 2 edges per warp-iter (1 per half-warp slot)
    for (; p < hi; p += 2) {
        const int slot = p + eslot;
        const bool valid = slot < hi;
        const int sA = valid ? g_col[base + slot] : 0;
        const float4 ga = *(const float4*)&gl[sA*64 + ch];
        float e0 = lrelu_dot(ga, grv, attv);
        e0 += __shfl_xor_sync(0xffffffffu, e0, 1);
        e0 += __shfl_xor_sync(0xffffffffu, e0, 2);
        const float w0 = valid ? __expf(e0 - m0) : 0.f;
        den += w0;
        v.x = fmaf(w0, ga.x, v.x);
        v.y = fmaf(w0, ga.y, v.y);
        v.z = fmaf(w0, ga.z, v.z);
        v.w = fmaf(w0, ga.w, v.w);
    }
    // merge edge slots
    den += __shfl_xor_sync(0xffffffffu, den, 16);
    v.x += __shfl_xor_sync(0xffffffffu, v.x, 16);
    v.y += __shfl_xor_sync(0xffffffffu, v.y, 16);
    v.z += __shfl_xor_sync(0xffffffffu, v.z, 16);
    v.w += __shfl_xor_sync(0xffffffffu, v.w, 16);

    // cross-warp merge (same m0 -> plain add)
    if (half == 1 && lane < 16) { sden[nb][t] = den; sv[nb][t] = v; }
    __syncthreads();
    if (half == 0 && lane < 16) {
        den += sden[nb][t];
        const float4 vo = sv[nb][t];
        v.x += vo.x;  v.y += vo.y;  v.z += vo.z;  v.w += vo.w;
        const float inv = 1.f/den;
        const float4 cbv = *(const float4*)&cb[ch];
        float4 hv = *(float4*)&H[i*64 + ch];
        hv.x += v.x*inv + cbv.x;
        hv.y += v.y*inv + cbv.y;
        hv.z += v.z*inv + cbv.z;
        hv.w += v.w*inv + cbv.w;
        *(float4*)&H[i*64 + ch] = hv;
    }
}

// =====================================================================
// edge MLP: 16 lanes/edge, 4 warps/node (verified)
// =====================================================================
__global__ void __launch_bounds__(256)
k_edge(const float* __restrict__ We3, const float* __restrict__ be3, float* __restrict__ out)
{
    const int gw   = blockIdx.x*8 + (threadIdx.x >> 5);
    const int lane = threadIdx.x & 31;
    const int i    = gw >> 2;
    const int q    = gw & 3;
    const int sub  = lane >> 4;
    const int t    = lane & 15;
    const int ch   = t*4;

    const float4 w3 = *(const float4*)&We3[ch];
    const float4 bv = *(const float4*)&g_B2[i*64 + ch];
    const float4 cc = *(const float4*)&g_c2[ch];
    const float4 k0 = make_float4(bv.x+cc.x, bv.y+cc.y, bv.z+cc.z, bv.w+cc.w);
    const float  b3 = be3[0];

    const int cnt  = min(g_cnt[i], CAP);
    const int base = i*CAP;
    const int lo = (cnt*q) >> 2;
    const int hi = (cnt*(q+1)) >> 2;

    for (int sb = lo; sb < hi; sb += 4) {
        const int slotA = sb + sub;
        const int slotB = sb + 2 + sub;
        const bool vA = slotA < hi;
        const bool vB = slotB < hi;
        const int sA = vA ? g_col[base + slotA] : 0;
        const int sB = vB ? g_col[base + slotB] : 0;
        const float4 aA = *(const float4*)&g_A2[sA*64 + ch];
        const float4 aB = *(const float4*)&g_A2[sB*64 + ch];
        float pA = fmaxf(aA.x + k0.x, 0.f)*w3.x;
        pA = fmaf(fmaxf(aA.y + k0.y, 0.f), w3.y, pA);
        pA = fmaf(fmaxf(aA.z + k0.z, 0.f), w3.z, pA);
        pA = fmaf(fmaxf(aA.w + k0.w, 0.f), w3.w, pA);
        float pB = fmaxf(aB.x + k0.x, 0.f)*w3.x;
        pB = fmaf(fmaxf(aB.y + k0.y, 0.f), w3.y, pB);
        pB = fmaf(fmaxf(aB.z + k0.z, 0.f), w3.z, pB);
        pB = fmaf(fmaxf(aB.w + k0.w, 0.f), w3.w, pB);
#pragma unroll
        for (int off = 1; off <= 8; off <<= 1) {
            pA += __shfl_xor_sync(0xffffffffu, pA, off);
            pB += __shfl_xor_sync(0xffffffffu, pB, off);
        }
        if (t == 0) {
            if (vA) out[(size_t)sA*NN + i] = 1.f/(1.f + __expf(-(pA + b3)));
            if (vB) out[(size_t)sB*NN + i] = 1.f/(1.f + __expf(-(pB + b3)));
        }
    }
}

// ---------------- launch ----------------
extern "C" void kernel_launch(void* const* d_in, const int* in_sizes, int n_in,
                              void* d_out, int out_size)
{
    const float* x    = (const float*)d_in[0];
    const int*   src  = (const int*)  d_in[2];
    const int*   dst  = (const int*)  d_in[3];
    const float* W1   = (const float*)d_in[4];
    const float* b1   = (const float*)d_in[5];
    const float* W2   = (const float*)d_in[6];
    const float* b2   = (const float*)d_in[7];
    const float* Wl1  = (const float*)d_in[8];
    const float* bl1  = (const float*)d_in[9];
    const float* Wr1  = (const float*)d_in[10];
    const float* br1  = (const float*)d_in[11];
    const float* att1 = (const float*)d_in[12];
    const float* cb1  = (const float*)d_in[13];
    const float* W4   = (const float*)d_in[14];
    const float* b4   = (const float*)d_in[15];
    const float* Wl2  = (const float*)d_in[16];
    const float* bl2  = (const float*)d_in[17];
    const float* Wr2  = (const float*)d_in[18];
    const float* br2  = (const float*)d_in[19];
    const float* att2 = (const float*)d_in[20];
    const float* cb2  = (const float*)d_in[21];
    const float* W5   = (const float*)d_in[22];
    const float* b5   = (const float*)d_in[23];
    const float* We1  = (const float*)d_in[24];
    const float* be1  = (const float*)d_in[25];
    const float* We2  = (const float*)d_in[26];
    const float* be2  = (const float*)d_in[27];
    const float* We3  = (const float*)d_in[28];
    const float* be3  = (const float*)d_in[29];
    const int E = in_sizes[2];

    void* p;
    float *pt1, *pt2, *pA2, *pB2, *pWca, *pWcb, *ph;
    cudaGetSymbolAddress(&p, g_t1);  pt1 = (float*)p;
    cudaGetSymbolAddress(&p, g_t2);  pt2 = (float*)p;
    cudaGetSymbolAddress(&p, g_A2);  pA2 = (float*)p;
    cudaGetSymbolAddress(&p, g_B2);  pB2 = (float*)p;
    cudaGetSymbolAddress(&p, g_Wca); pWca = (float*)p;
    cudaGetSymbolAddress(&p, g_Wcb); pWcb = (float*)p;
    cudaGetSymbolAddress(&p, g_h);   ph = (float*)p;

    cudaGetSymbolAddress(&p, g_cnt);
    cudaMemsetAsync(p, 0, NN*sizeof(int), 0);

    // fork: zero the 64MB output on a parallel branch
    cudaStream_t s2 = 0;
    cudaEvent_t evF = 0, evJ = 0;
    bool forked = false;
    if (cudaStreamCreateWithFlags(&s2, cudaStreamNonBlocking) == cudaSuccess &&
        cudaEventCreateWithFlags(&evF, cudaEventDisableTiming) == cudaSuccess &&
        cudaEventCreateWithFlags(&evJ, cudaEventDisableTiming) == cudaSuccess) {
        cudaEventRecord(evF, 0);
        cudaStreamWaitEvent(s2, evF, 0);
        cudaMemsetAsync(d_out, 0, (size_t)out_size * sizeof(float), s2);
        cudaEventRecord(evJ, s2);
        forked = true;
    } else {
        cudaMemsetAsync(d_out, 0, (size_t)out_size * sizeof(float), 0);
    }

    k_prep<<<322, 256>>>(x, src, dst, W1, b1, W2, b2, Wl1, bl1, Wr1, br1,
                         We1, be1, We2, be2, E);

    k_gat<<<1024, 256>>>(pt1, pt2, att1, cb1, ph);
    k_resdual<<<512, 256>>>(ph, W4, b4, Wl2, bl2, Wr2, br2, pt1, pt2);

    k_gat<<<1024, 256>>>(pt1, pt2, att2, cb2, ph);
    k_resdual<<<512, 256>>>(ph, W5, b5, pWca, nullptr, pWcb, nullptr, pA2, pB2);

    if (forked) cudaStreamWaitEvent(0, evJ, 0);
    k_edge<<<2048, 256>>>(We3, be3, (float*)d_out);
}